// round 1
// baseline (speedup 1.0000x reference)
#include <cuda_runtime.h>
#include <math.h>

// Shapes (fixed by the problem)
#define Bv 16
#define Tv 512
#define Sv 2048
#define Dv 768

// Scratch (allocation-free rule: __device__ globals)
__device__ float g_score[Bv * Sv];
__device__ float g_weight[Bv * Sv];
__device__ float g_pctx[Bv * 4 * Dv];
__device__ float g_ctx[Bv * Dv];
__device__ float g_cg[Bv];

// ---------------------------------------------------------------------------
// Kernel A: enc_score[b,s] = dot(encoder_outputs[b,s,:], w_ptr[D:2D]), masked.
// One warp per (b,s) row; float4 vectorized.
// ---------------------------------------------------------------------------
__global__ void k_enc_score(const float* __restrict__ enc,
                            const int* __restrict__ mask,
                            const float* __restrict__ w_ptr) {
    int gw = (blockIdx.x * blockDim.x + threadIdx.x) >> 5;
    int lane = threadIdx.x & 31;
    if (gw >= Bv * Sv) return;
    const float4* row = reinterpret_cast<const float4*>(enc) + (size_t)gw * (Dv / 4);
    const float4* w   = reinterpret_cast<const float4*>(w_ptr + Dv);
    float acc = 0.f;
#pragma unroll
    for (int i = 0; i < (Dv / 4) / 32; i++) {            // 6 iters
        float4 a  = row[lane + 32 * i];
        float4 ww = __ldg(&w[lane + 32 * i]);
        acc += a.x * ww.x + a.y * ww.y + a.z * ww.z + a.w * ww.w;
    }
#pragma unroll
    for (int o = 16; o; o >>= 1) acc += __shfl_xor_sync(0xffffffffu, acc, o);
    if (lane == 0) g_score[gw] = mask[gw] ? acc : -1e9f;
}

// ---------------------------------------------------------------------------
// Kernel B: per-batch softmax over S=2048. One block of 1024 threads per b.
// ---------------------------------------------------------------------------
__global__ void k_softmax() {
    int b = blockIdx.x;
    int tid = threadIdx.x;                                // 1024 threads
    float v0 = g_score[b * Sv + tid];
    float v1 = g_score[b * Sv + tid + 1024];

    __shared__ float redm[32];
    __shared__ float reds[32];

    float m = fmaxf(v0, v1);
#pragma unroll
    for (int o = 16; o; o >>= 1) m = fmaxf(m, __shfl_xor_sync(0xffffffffu, m, o));
    if ((tid & 31) == 0) redm[tid >> 5] = m;
    __syncthreads();
    if (tid < 32) {
        float x = redm[tid];
#pragma unroll
        for (int o = 16; o; o >>= 1) x = fmaxf(x, __shfl_xor_sync(0xffffffffu, x, o));
        if (tid == 0) redm[0] = x;
    }
    __syncthreads();
    float M = redm[0];

    float e0 = expf(v0 - M);
    float e1 = expf(v1 - M);
    float s = e0 + e1;
#pragma unroll
    for (int o = 16; o; o >>= 1) s += __shfl_xor_sync(0xffffffffu, s, o);
    if ((tid & 31) == 0) reds[tid >> 5] = s;
    __syncthreads();
    if (tid < 32) {
        float x = reds[tid];
#pragma unroll
        for (int o = 16; o; o >>= 1) x += __shfl_xor_sync(0xffffffffu, x, o);
        if (tid == 0) reds[0] = x;
    }
    __syncthreads();
    float inv = 1.f / reds[0];
    g_weight[b * Sv + tid]        = e0 * inv;
    g_weight[b * Sv + tid + 1024] = e1 * inv;
}

// ---------------------------------------------------------------------------
// Kernel C: partial context. grid = (6 d-chunks, 4 s-chunks, B), 128 threads.
// g_pctx[b, sc, d] = sum over its 512-row s-chunk of w[b,s]*enc[b,s,d].
// Deterministic (no atomics).
// ---------------------------------------------------------------------------
__global__ void k_ctx_partial(const float* __restrict__ enc) {
    int dc = blockIdx.x, sc = blockIdx.y, b = blockIdx.z;
    int d = dc * 128 + threadIdx.x;

    __shared__ float w[512];
    for (int i = threadIdx.x; i < 512; i += 128)
        w[i] = g_weight[b * Sv + sc * 512 + i];
    __syncthreads();

    const float* e = enc + ((size_t)b * Sv + (size_t)sc * 512) * Dv + d;
    float acc = 0.f;
#pragma unroll 8
    for (int s = 0; s < 512; s++)
        acc += w[s] * e[(size_t)s * Dv];
    g_pctx[((b * 4) + sc) * Dv + d] = acc;
}

// ---------------------------------------------------------------------------
// Kernel D: reduce 4 partials -> g_ctx[b,:], and g_cg[b] = ctx . w_gen[D:2D].
// One block of 256 threads per b.
// ---------------------------------------------------------------------------
__global__ void k_ctx_reduce(const float* __restrict__ w_gen) {
    int b = blockIdx.x, tid = threadIdx.x;
    float dot = 0.f;
    for (int d = tid; d < Dv; d += 256) {
        float c = g_pctx[(b * 4 + 0) * Dv + d]
                + g_pctx[(b * 4 + 1) * Dv + d]
                + g_pctx[(b * 4 + 2) * Dv + d]
                + g_pctx[(b * 4 + 3) * Dv + d];
        g_ctx[b * Dv + d] = c;
        dot += c * __ldg(&w_gen[Dv + d]);
    }
    __shared__ float red[8];
#pragma unroll
    for (int o = 16; o; o >>= 1) dot += __shfl_xor_sync(0xffffffffu, dot, o);
    if ((tid & 31) == 0) red[tid >> 5] = dot;
    __syncthreads();
    if (tid == 0) {
        float s = 0.f;
#pragma unroll
        for (int i = 0; i < 8; i++) s += red[i];
        g_cg[b] = s;
    }
}

// ---------------------------------------------------------------------------
// Kernel F: one block per (b,t). Writes pointer_weights row (broadcast of
// g_weight[b,:]), context row (broadcast of g_ctx[b,:]), and p_gen[b,t]
// (sigmoid(dec[b,t].g_d + g_cg[b] + b_gen)). 256 threads.
// Output layout: [pw (B*T*S)] [p_gen (B*T)] [context (B*T*D)]
// ---------------------------------------------------------------------------
__global__ void k_out(const float* __restrict__ dec,
                      const float* __restrict__ w_gen,
                      const float* __restrict__ b_gen,
                      float* __restrict__ out) {
    int bt = blockIdx.x;
    int b = bt >> 9;                                      // T = 512
    int tid = threadIdx.x;

    // p_gen partial dot: 192 float4 per dec row
    const float4* drow = reinterpret_cast<const float4*>(dec) + (size_t)bt * (Dv / 4);
    float acc = 0.f;
    if (tid < Dv / 4) {
        float4 a = drow[tid];
        float4 g = __ldg(reinterpret_cast<const float4*>(w_gen) + tid);
        acc = a.x * g.x + a.y * g.y + a.z * g.z + a.w * g.w;
    }
    __shared__ float red[8];
#pragma unroll
    for (int o = 16; o; o >>= 1) acc += __shfl_xor_sync(0xffffffffu, acc, o);
    if ((tid & 31) == 0) red[tid >> 5] = acc;
    __syncthreads();

    // pointer_weights broadcast: 512 float4 per row, 2 per thread
    float4* pw4 = reinterpret_cast<float4*>(out) + (size_t)bt * (Sv / 4);
    const float4* wrow = reinterpret_cast<const float4*>(g_weight) + (size_t)b * (Sv / 4);
#pragma unroll
    for (int i = 0; i < 2; i++)
        pw4[tid + 256 * i] = __ldg(&wrow[tid + 256 * i]);

    // context broadcast: 192 float4 per row
    float* ctx_base = out + (size_t)Bv * Tv * Sv + (size_t)Bv * Tv;
    float4* ctx4 = reinterpret_cast<float4*>(ctx_base) + (size_t)bt * (Dv / 4);
    const float4* crow = reinterpret_cast<const float4*>(g_ctx) + (size_t)b * (Dv / 4);
    if (tid < Dv / 4) ctx4[tid] = __ldg(&crow[tid]);

    if (tid == 0) {
        float s = red[0] + red[1] + red[2] + red[3] + red[4] + red[5] + red[6] + red[7];
        float x = s + g_cg[b] + __ldg(&b_gen[0]);
        out[(size_t)Bv * Tv * Sv + bt] = 1.f / (1.f + expf(-x));
    }
}

// ---------------------------------------------------------------------------
// Launch
// ---------------------------------------------------------------------------
extern "C" void kernel_launch(void* const* d_in, const int* in_sizes, int n_in,
                              void* d_out, int out_size) {
    const float* dec    = (const float*)d_in[0];  // (B,T,D)
    const float* enc    = (const float*)d_in[1];  // (B,S,D)
    const int*   mask   = (const int*)d_in[2];    // (B,S)
    const float* w_ptr  = (const float*)d_in[3];  // (2D,)
    // d_in[4] = b_ptr (zeros, cancels in softmax; unused)
    const float* w_gen  = (const float*)d_in[5];  // (2D,)
    const float* b_gen  = (const float*)d_in[6];  // (1,)
    float* out = (float*)d_out;

    // A: 32768 warps -> 4096 blocks x 256
    k_enc_score<<<(Bv * Sv * 32) / 256, 256>>>(enc, mask, w_ptr);
    // B: per-batch softmax
    k_softmax<<<Bv, 1024>>>();
    // C: partial context
    dim3 gc(Dv / 128, 4, Bv);
    k_ctx_partial<<<gc, 128>>>(enc);
    // D: reduce + context.g_e
    k_ctx_reduce<<<Bv, 256>>>(w_gen);
    // F: outputs
    k_out<<<Bv * Tv, 256>>>(dec, w_gen, b_gen, out);
}

// round 3
// speedup vs baseline: 1.2119x; 1.2119x over previous
#include <cuda_runtime.h>
#include <math.h>

#define Bv 16
#define Tv 512
#define Sv 2048
#define Dv 768
#define SC 16            // s-chunks in context pass
#define TCH 16           // t-rows per output block

// Scratch (__device__ globals: allocation-free rule)
__device__ float g_score[Bv * Sv];
__device__ float g_weight[Bv * Sv];
__device__ float g_pctx[Bv * SC * Dv];
__device__ float g_ctx[Bv * Dv];
__device__ float g_cg[Bv];

// ---------------------------------------------------------------------------
// A: enc_score[b,s] = dot(enc[b,s,:], w_ptr[D:2D]), masked. 1 warp / row.
// ---------------------------------------------------------------------------
__global__ void k_enc_score(const float* __restrict__ enc,
                            const int* __restrict__ mask,
                            const float* __restrict__ w_ptr) {
    int gw = (blockIdx.x * blockDim.x + threadIdx.x) >> 5;
    int lane = threadIdx.x & 31;
    if (gw >= Bv * Sv) return;
    const float4* row = reinterpret_cast<const float4*>(enc) + (size_t)gw * (Dv / 4);
    const float4* w   = reinterpret_cast<const float4*>(w_ptr + Dv);
    float acc = 0.f;
#pragma unroll
    for (int i = 0; i < (Dv / 4) / 32; i++) {            // 6 iters
        float4 a  = row[lane + 32 * i];
        float4 ww = __ldg(&w[lane + 32 * i]);
        acc += a.x * ww.x + a.y * ww.y + a.z * ww.z + a.w * ww.w;
    }
#pragma unroll
    for (int o = 16; o; o >>= 1) acc += __shfl_xor_sync(0xffffffffu, acc, o);
    if (lane == 0) g_score[gw] = mask[gw] ? acc : -1e9f;
}

// ---------------------------------------------------------------------------
// B: per-batch softmax over S=2048. 1 block of 1024 per b.
// ---------------------------------------------------------------------------
__global__ void k_softmax() {
    int b = blockIdx.x;
    int tid = threadIdx.x;
    float v0 = g_score[b * Sv + tid];
    float v1 = g_score[b * Sv + tid + 1024];

    __shared__ float redm[32];
    __shared__ float reds[32];

    float m = fmaxf(v0, v1);
#pragma unroll
    for (int o = 16; o; o >>= 1) m = fmaxf(m, __shfl_xor_sync(0xffffffffu, m, o));
    if ((tid & 31) == 0) redm[tid >> 5] = m;
    __syncthreads();
    if (tid < 32) {
        float x = redm[tid];
#pragma unroll
        for (int o = 16; o; o >>= 1) x = fmaxf(x, __shfl_xor_sync(0xffffffffu, x, o));
        if (tid == 0) redm[0] = x;
    }
    __syncthreads();
    float M = redm[0];

    float e0 = expf(v0 - M);
    float e1 = expf(v1 - M);
    float s = e0 + e1;
#pragma unroll
    for (int o = 16; o; o >>= 1) s += __shfl_xor_sync(0xffffffffu, s, o);
    if ((tid & 31) == 0) reds[tid >> 5] = s;
    __syncthreads();
    if (tid < 32) {
        float x = reds[tid];
#pragma unroll
        for (int o = 16; o; o >>= 1) x += __shfl_xor_sync(0xffffffffu, x, o);
        if (tid == 0) reds[0] = x;
    }
    __syncthreads();
    float inv = 1.f / reds[0];
    g_weight[b * Sv + tid]        = e0 * inv;
    g_weight[b * Sv + tid + 1024] = e1 * inv;
}

// ---------------------------------------------------------------------------
// C: partial context, float4. grid=(SC, B), 192 threads (each owns 4 d's).
// Each block sums 128 s-rows: pctx[b,sc,:] += w[s] * enc[b,s,:].
// ---------------------------------------------------------------------------
__global__ void k_ctx_partial(const float* __restrict__ enc) {
    int sc = blockIdx.x, b = blockIdx.y;
    int tid = threadIdx.x;                                // 0..191

    __shared__ float w[Sv / SC];                          // 128
    if (tid < Sv / SC) w[tid] = g_weight[b * Sv + sc * (Sv / SC) + tid];
    __syncthreads();

    const float4* e = reinterpret_cast<const float4*>(enc)
                    + ((size_t)b * Sv + (size_t)sc * (Sv / SC)) * (Dv / 4) + tid;
    float4 acc = make_float4(0.f, 0.f, 0.f, 0.f);
#pragma unroll 8
    for (int s = 0; s < Sv / SC; s++) {
        float ws = w[s];
        float4 v = e[(size_t)s * (Dv / 4)];
        acc.x += ws * v.x; acc.y += ws * v.y;
        acc.z += ws * v.z; acc.w += ws * v.w;
    }
    reinterpret_cast<float4*>(g_pctx)[((size_t)(b * SC + sc)) * (Dv / 4) + tid] = acc;
}

// ---------------------------------------------------------------------------
// D: reduce SC partials -> g_ctx[b,:]; g_cg[b] = ctx . w_gen[D:2D].
// 1 block of 768 per b, one thread per d.
// ---------------------------------------------------------------------------
__global__ void k_ctx_reduce(const float* __restrict__ w_gen) {
    int b = blockIdx.x, d = threadIdx.x;
    float c = 0.f;
#pragma unroll
    for (int p = 0; p < SC; p++)
        c += g_pctx[(size_t)(b * SC + p) * Dv + d];
    g_ctx[b * Dv + d] = c;

    float dot = c * __ldg(&w_gen[Dv + d]);
    __shared__ float red[24];
#pragma unroll
    for (int o = 16; o; o >>= 1) dot += __shfl_xor_sync(0xffffffffu, dot, o);
    if ((d & 31) == 0) red[d >> 5] = dot;
    __syncthreads();
    if (d == 0) {
        float s = 0.f;
#pragma unroll
        for (int i = 0; i < 24; i++) s += red[i];
        g_cg[b] = s;
    }
}

// ---------------------------------------------------------------------------
// F: one block per (b, 16-t chunk). Stage weight row + ctx row in smem once,
// broadcast to 16 output rows; p_gen via per-warp dec dots.
// Output layout: [pw (B*T*S)] [p_gen (B*T)] [context (B*T*D)]
// ---------------------------------------------------------------------------
__global__ void k_out(const float* __restrict__ dec,
                      const float* __restrict__ w_gen,
                      const float* __restrict__ b_gen,
                      float* __restrict__ out) {
    int b = blockIdx.y;
    int t0 = blockIdx.x * TCH;
    int tid = threadIdx.x;                                // 256 threads
    int warp = tid >> 5, lane = tid & 31;

    __shared__ float sw[Sv];                              // 8KB weight row
    __shared__ float sc[Dv];                              // 3KB ctx row
    __shared__ float spg[TCH];

    // stage broadcast rows
    float4* sw4 = reinterpret_cast<float4*>(sw);
    const float4* gw4 = reinterpret_cast<const float4*>(g_weight) + (size_t)b * (Sv / 4);
#pragma unroll
    for (int i = 0; i < 2; i++) sw4[tid + 256 * i] = gw4[tid + 256 * i];
    float4* sc4 = reinterpret_cast<float4*>(sc);
    const float4* gc4 = reinterpret_cast<const float4*>(g_ctx) + (size_t)b * (Dv / 4);
    if (tid < Dv / 4) sc4[tid] = gc4[tid];

    // p_gen dec-dots: 8 warps x 2 t-rows each
#pragma unroll
    for (int k = 0; k < 2; k++) {
        int tt = warp * 2 + k;
        size_t bt = (size_t)b * Tv + t0 + tt;
        const float4* drow = reinterpret_cast<const float4*>(dec) + bt * (Dv / 4);
        const float4* g4   = reinterpret_cast<const float4*>(w_gen);
        float acc = 0.f;
#pragma unroll
        for (int i = 0; i < 6; i++) {
            float4 a = __ldcs(&drow[lane + 32 * i]);
            float4 g = __ldg(&g4[lane + 32 * i]);
            acc += a.x * g.x + a.y * g.y + a.z * g.z + a.w * g.w;
        }
#pragma unroll
        for (int o = 16; o; o >>= 1) acc += __shfl_xor_sync(0xffffffffu, acc, o);
        if (lane == 0) spg[tt] = acc;
    }
    __syncthreads();

    // broadcast writes (streaming stores: no reuse of outputs)
    float* ctx_base = out + (size_t)Bv * Tv * Sv + (size_t)Bv * Tv;
#pragma unroll 4
    for (int tt = 0; tt < TCH; tt++) {
        size_t bt = (size_t)b * Tv + t0 + tt;
        float4* pw4 = reinterpret_cast<float4*>(out) + bt * (Sv / 4);
#pragma unroll
        for (int i = 0; i < 2; i++)
            __stcs(&pw4[tid + 256 * i], sw4[tid + 256 * i]);
        if (tid < Dv / 4) {
            float4* c4 = reinterpret_cast<float4*>(ctx_base) + bt * (Dv / 4);
            __stcs(&c4[tid], sc4[tid]);
        }
    }

    if (tid < TCH) {
        float x = spg[tid] + g_cg[b] + __ldg(&b_gen[0]);
        out[(size_t)Bv * Tv * Sv + (size_t)b * Tv + t0 + tid] = 1.f / (1.f + expf(-x));
    }
}

// ---------------------------------------------------------------------------
extern "C" void kernel_launch(void* const* d_in, const int* in_sizes, int n_in,
                              void* d_out, int out_size) {
    const float* dec    = (const float*)d_in[0];
    const float* enc    = (const float*)d_in[1];
    const int*   mask   = (const int*)d_in[2];
    const float* w_ptr  = (const float*)d_in[3];
    // d_in[4] = b_ptr (zeros; cancels in softmax)
    const float* w_gen  = (const float*)d_in[5];
    const float* b_gen  = (const float*)d_in[6];
    float* out = (float*)d_out;

    k_enc_score<<<(Bv * Sv * 32) / 256, 256>>>(enc, mask, w_ptr);
    k_softmax<<<Bv, 1024>>>();
    dim3 gc(SC, Bv);
    k_ctx_partial<<<gc, 192>>>(enc);
    k_ctx_reduce<<<Bv, Dv>>>(w_gen);
    dim3 gf(Tv / TCH, Bv);
    k_out<<<gf, 256>>>(dec, w_gen, b_gen, out);
}